// round 1
// baseline (speedup 1.0000x reference)
#include <cuda_runtime.h>
#include <cuda_bf16.h>
#include <cstdint>

// ---------------------------------------------------------------------------
// Problem: quantized "LUT" conv. lut[a+128,b+128] == a*b exactly, so this is
// a plain int8 conv with dynamic scales:
//   T_f = 0.95*3.0 + 0.05*max|x| ; T_w = 0.95*0.3 + 0.05*max|w|
//   s_x = T_f/127 ; s_w = T_w/127
//   qx = clip(rint(x/s_x),-128,127) ; qw = clip(rint(w/s_w),-128,127)
//   out = (int8conv(qx,qw)) * (s_x*s_w) + bias
// Integer accumulation is bit-identical to the f32 reference (all partial
// sums are integers < 2^24).
// Shapes: x(8,64,28,28) w(64,64,3,3) pad=1 stride=1 -> out(8,64,28,28) f32.
// ---------------------------------------------------------------------------

#define B_  8
#define C_  64
#define H_  28
#define W_  28
#define K_  3
#define HP  30   // padded
#define WP  30

// scratch (device globals: allocation-free). g_qx zero-initialized at module
// load; padding border is never written so it stays zero across all launches.
__device__ unsigned int g_absmax[2];
__device__ float        g_scales[3];                 // s_x, s_w, s_x*s_w
__device__ signed char  g_qx[B_ * HP * WP * C_];     // NHWC, padded
__device__ signed char  g_qw[C_ * K_ * K_ * C_];     // [co][kh][kw][ci]

// ---------------------------------------------------------------------------
__global__ void reset_kernel() {
    if (threadIdx.x == 0) { g_absmax[0] = 0u; g_absmax[1] = 0u; }
}

__global__ void absmax_kernel(const float* __restrict__ p, int n, int slot) {
    float m = 0.0f;
    for (int i = blockIdx.x * blockDim.x + threadIdx.x; i < n;
         i += gridDim.x * blockDim.x)
        m = fmaxf(m, fabsf(p[i]));
    #pragma unroll
    for (int o = 16; o; o >>= 1)
        m = fmaxf(m, __shfl_xor_sync(0xffffffffu, m, o));
    if ((threadIdx.x & 31) == 0)
        atomicMax(&g_absmax[slot], __float_as_uint(m));  // vals >=0: uint order ok
}

__global__ void finalize_kernel() {
    float mx = __uint_as_float(g_absmax[0]);
    float mw = __uint_as_float(g_absmax[1]);
    // 0.95*3.0 = 2.85, 0.95*0.3 = 0.285, 1-0.95 = 0.05 (f32)
    float Tf = __fadd_rn(2.85f,  __fmul_rn(0.05f, mx));
    float Tw = __fadd_rn(0.285f, __fmul_rn(0.05f, mw));
    float sx = __fdiv_rn(Tf, 127.0f);
    float sw = __fdiv_rn(Tw, 127.0f);
    g_scales[0] = sx;
    g_scales[1] = sw;
    g_scales[2] = __fmul_rn(sx, sw);
}

__global__ void quantx_kernel(const float* __restrict__ x) {
    int i = blockIdx.x * blockDim.x + threadIdx.x;
    if (i >= B_ * C_ * H_ * W_) return;
    float s = g_scales[0];
    int c = i & 63;
    int r = i >> 6;
    int w = r % W_; r /= W_;
    int h = r % H_;
    int b = r / H_;
    float v = x[((b * C_ + c) * H_ + h) * W_ + w];
    float q = rintf(__fdiv_rn(v, s));
    q = fminf(fmaxf(q, -128.0f), 127.0f);
    g_qx[((b * HP + h + 1) * WP + (w + 1)) * C_ + c] = (signed char)(int)q;
}

__global__ void quantw_kernel(const float* __restrict__ wgt) {
    int i = blockIdx.x * blockDim.x + threadIdx.x;
    if (i >= C_ * C_ * K_ * K_) return;
    float s = g_scales[1];
    int ci = i & 63;
    int r  = i >> 6;
    int kw = r % K_; r /= K_;
    int kh = r % K_;
    int co = r / K_;
    float v = wgt[((co * C_ + ci) * K_ + kh) * K_ + kw];
    float q = rintf(__fdiv_rn(v, s));
    q = fminf(fmaxf(q, -128.0f), 127.0f);
    g_qw[((co * K_ + kh) * K_ + kw) * C_ + ci] = (signed char)(int)q;
}

// ---------------------------------------------------------------------------
// Conv: one block per (oh, b). 256 threads: co = tid&63, owg = tid>>6.
// Each thread produces 7 outputs (ow = owg*7 + i). Weights staged in smem at
// a 592-byte row pitch (37 x 16B, odd -> conflict-free lane-strided LDS.128).
// X rows broadcast from smem (all lanes of a warp share owg -> same address).
// Weight values are register-reused across the 7 ow positions.
// ---------------------------------------------------------------------------
#define WROW_W 148                       // words per co row in smem (144 + 4 pad)
#define XROW_W (WP * C_ / 4)             // 480 words per padded x row

__global__ __launch_bounds__(256) void conv_kernel(
    const float* __restrict__ bias, float* __restrict__ out)
{
    __shared__ int s_qw[C_ * WROW_W];    // 37888 B
    __shared__ int s_x[3 * XROW_W];      // 5760 B

    const int oh  = blockIdx.x;
    const int b   = blockIdx.y;
    const int tid = threadIdx.x;

    // stage weights: 64*144 words, contiguous global reads, padded smem pitch
    const int* gw = (const int*)g_qw;
    for (int idx = tid; idx < C_ * 144; idx += 256) {
        int co = idx / 144;
        int j  = idx - co * 144;
        s_qw[co * WROW_W + j] = gw[idx];
    }
    // stage 3 padded x rows (oh .. oh+2)
    const int* gx = (const int*)g_qx + (b * HP + oh) * XROW_W;
    for (int idx = tid; idx < 3 * XROW_W; idx += 256)
        s_x[idx] = gx[idx];
    __syncthreads();

    const float prod = g_scales[2];
    const int co  = tid & 63;
    const int owg = tid >> 6;
    const int* wbase = s_qw + co * WROW_W;
    const float bco  = bias[co];
    float* obase = out + ((b * C_ + co) * H_ + oh) * W_;

    int acc[7];
    #pragma unroll
    for (int i = 0; i < 7; i++) acc[i] = 0;

    #pragma unroll
    for (int kh = 0; kh < 3; kh++) {
        const int* xrow = s_x + kh * XROW_W + owg * 7 * 16;
        const int* wrow = wbase + kh * 48;
        #pragma unroll
        for (int jj = 0; jj < 12; jj++) {
            // one 16B weight chunk, reused across 7 outputs
            int4 w4 = *(const int4*)(wrow + jj * 4);
            #pragma unroll
            for (int i = 0; i < 7; i++) {
                int4 x4 = *(const int4*)(xrow + i * 16 + jj * 4);
                int a = acc[i];
                a = __dp4a(x4.x, w4.x, a);
                a = __dp4a(x4.y, w4.y, a);
                a = __dp4a(x4.z, w4.z, a);
                a = __dp4a(x4.w, w4.w, a);
                acc[i] = a;
            }
        }
    }

    #pragma unroll
    for (int i = 0; i < 7; i++) {
        int ow = owg * 7 + i;
        obase[ow] = __fadd_rn(__fmul_rn((float)acc[i], prod), bco);
    }
}

// ---------------------------------------------------------------------------
extern "C" void kernel_launch(void* const* d_in, const int* in_sizes, int n_in,
                              void* d_out, int out_size)
{
    const float* x    = (const float*)d_in[0];   // (8,64,28,28)
    const float* wgt  = (const float*)d_in[1];   // (64,64,3,3)
    const float* bias = (const float*)d_in[2];   // (64,)
    // d_in[3] = lut: provably lut[a+128,b+128] == a*b -> folded into int MAC
    float* out = (float*)d_out;

    const int nx = B_ * C_ * H_ * W_;            // 401408
    const int nw = C_ * C_ * K_ * K_;            // 36864

    reset_kernel<<<1, 32>>>();
    absmax_kernel<<<392, 256>>>(x,   nx, 0);
    absmax_kernel<<<36,  256>>>(wgt, nw, 1);
    finalize_kernel<<<1, 1>>>();
    quantx_kernel<<<(nx + 255) / 256, 256>>>(x);
    quantw_kernel<<<(nw + 255) / 256, 256>>>(wgt);
    conv_kernel<<<dim3(H_, B_), 256>>>(bias, out);
    (void)in_sizes; (void)n_in; (void)out_size;
}

// round 2
// speedup vs baseline: 1.1764x; 1.1764x over previous
#include <cuda_runtime.h>
#include <cuda_bf16.h>
#include <cstdint>

// ---------------------------------------------------------------------------
// Quantized "LUT" conv. lut[a+128,b+128] == a*b exactly -> plain int8 conv:
//   T_f = 2.85 + 0.05*max|x| ; T_w = 0.285 + 0.05*max|w|
//   s_x = T_f/127 ; s_w = T_w/127
//   out = int8conv(clip(rint(x/s_x)), clip(rint(w/s_w))) * (s_x*s_w) + bias
// Integer accumulation is bit-identical to the f32 reference (partial sums
// are integers < 2^24). Shapes: x(8,64,28,28) w(64,64,3,3) pad=1 -> same.
//
// R2: collapsed 7 graph nodes -> 3 (launch overhead ~3.3us/node dominated).
// ---------------------------------------------------------------------------

#define B_  8
#define C_  64
#define H_  28
#define W_  28
#define K_  3
#define HP  30
#define WP  30
#define NX  (B_ * C_ * H_ * W_)   // 401408
#define NW  (C_ * C_ * K_ * K_)   // 36864

// device scratch (allocation-free). g_qx zero-init at load; padding border is
// never written so it stays zero. absmax/count reset by the last block each
// launch -> deterministic across graph replays.
__device__ unsigned int g_absmax[2];
__device__ unsigned int g_count;
__device__ float        g_scales[3];                 // s_x, s_w, s_x*s_w
__device__ signed char  g_qx[B_ * HP * WP * C_];     // NHWC padded
__device__ signed char  g_qw[C_ * K_ * K_ * C_];     // [co][kh][kw][ci]

// ---------------------------------------------------------------------------
// Node 1: absmax over x and w + fenced last-block finalize (+ state reset)
// ---------------------------------------------------------------------------
#define AB_GRID 148

__global__ __launch_bounds__(256) void absmax_finalize_kernel(
    const float* __restrict__ x, const float* __restrict__ w)
{
    const int tid = blockIdx.x * blockDim.x + threadIdx.x;
    const int stride = AB_GRID * 256;

    float mx = 0.0f;
    const float4* x4 = (const float4*)x;
    for (int i = tid; i < NX / 4; i += stride) {
        float4 v = x4[i];
        mx = fmaxf(mx, fmaxf(fmaxf(fabsf(v.x), fabsf(v.y)),
                             fmaxf(fabsf(v.z), fabsf(v.w))));
    }
    float mw = 0.0f;
    const float4* w4 = (const float4*)w;
    for (int i = tid; i < NW / 4; i += stride) {
        float4 v = w4[i];
        mw = fmaxf(mw, fmaxf(fmaxf(fabsf(v.x), fabsf(v.y)),
                             fmaxf(fabsf(v.z), fabsf(v.w))));
    }
    #pragma unroll
    for (int o = 16; o; o >>= 1) {
        mx = fmaxf(mx, __shfl_xor_sync(0xffffffffu, mx, o));
        mw = fmaxf(mw, __shfl_xor_sync(0xffffffffu, mw, o));
    }
    if ((threadIdx.x & 31) == 0) {
        atomicMax(&g_absmax[0], __float_as_uint(mx));   // vals >= 0
        atomicMax(&g_absmax[1], __float_as_uint(mw));
    }
    __syncthreads();
    if (threadIdx.x == 0) {
        __threadfence();
        unsigned int done = atomicAdd(&g_count, 1u);
        if (done == AB_GRID - 1) {
            __threadfence();
            float amx = __uint_as_float(g_absmax[0]);
            float amw = __uint_as_float(g_absmax[1]);
            float Tf = __fadd_rn(2.85f,  __fmul_rn(0.05f, amx));
            float Tw = __fadd_rn(0.285f, __fmul_rn(0.05f, amw));
            float sx = __fdiv_rn(Tf, 127.0f);
            float sw = __fdiv_rn(Tw, 127.0f);
            g_scales[0] = sx;
            g_scales[1] = sw;
            g_scales[2] = __fmul_rn(sx, sw);
            // reset for next graph replay
            g_absmax[0] = 0u;
            g_absmax[1] = 0u;
            g_count     = 0u;
        }
    }
}

// ---------------------------------------------------------------------------
// Node 2: fused quantize of x (NCHW f32 -> padded NHWC i8) and w
// ---------------------------------------------------------------------------
__global__ __launch_bounds__(256) void quant_fused_kernel(
    const float* __restrict__ x, const float* __restrict__ wgt)
{
    int i = blockIdx.x * blockDim.x + threadIdx.x;
    if (i < NX) {
        float s = g_scales[0];
        int c = i & 63;
        int r = i >> 6;
        int w = r % W_; r /= W_;
        int h = r % H_;
        int b = r / H_;
        float v = x[((b * C_ + c) * H_ + h) * W_ + w];
        float q = rintf(__fdiv_rn(v, s));
        q = fminf(fmaxf(q, -128.0f), 127.0f);
        g_qx[((b * HP + h + 1) * WP + (w + 1)) * C_ + c] = (signed char)(int)q;
    } else if (i < NX + NW) {
        int j = i - NX;
        float s = g_scales[1];
        int ci = j & 63;
        int r  = j >> 6;
        int kw = r % K_; r /= K_;
        int kh = r % K_;
        int co = r / K_;
        float v = wgt[((co * C_ + ci) * K_ + kh) * K_ + kw];
        float q = rintf(__fdiv_rn(v, s));
        q = fminf(fmaxf(q, -128.0f), 127.0f);
        g_qw[((co * K_ + kh) * K_ + kw) * C_ + ci] = (signed char)(int)q;
    }
}

// ---------------------------------------------------------------------------
// Node 3: conv. One block per (oh, b). 256 threads: co = tid&63, owg = tid>>6.
// Each thread makes 7 outputs. Weights in smem at 592B pitch (37x16B, odd ->
// conflict-free lane-strided LDS.128); x rows broadcast from smem; weight
// chunks register-reused across 7 ow positions.
// ---------------------------------------------------------------------------
#define WROW_W 148                       // words per co row (144 + 4 pad)
#define XROW_W (WP * C_ / 4)             // 480 words per padded x row

__global__ __launch_bounds__(256) void conv_kernel(
    const float* __restrict__ bias, float* __restrict__ out)
{
    __shared__ int s_qw[C_ * WROW_W];    // 37888 B
    __shared__ int s_x[3 * XROW_W];      // 5760 B

    const int oh  = blockIdx.x;
    const int b   = blockIdx.y;
    const int tid = threadIdx.x;

    const int* gw = (const int*)g_qw;
    for (int idx = tid; idx < C_ * 144; idx += 256) {
        int co = idx / 144;
        int j  = idx - co * 144;
        s_qw[co * WROW_W + j] = gw[idx];
    }
    const int* gx = (const int*)g_qx + (b * HP + oh) * XROW_W;
    for (int idx = tid; idx < 3 * XROW_W; idx += 256)
        s_x[idx] = gx[idx];
    __syncthreads();

    const float prod = g_scales[2];
    const int co  = tid & 63;
    const int owg = tid >> 6;
    const int* wbase = s_qw + co * WROW_W;
    const float bco  = bias[co];
    float* obase = out + ((b * C_ + co) * H_ + oh) * W_;

    int acc[7];
    #pragma unroll
    for (int i = 0; i < 7; i++) acc[i] = 0;

    #pragma unroll
    for (int kh = 0; kh < 3; kh++) {
        const int* xrow = s_x + kh * XROW_W + owg * 7 * 16;
        const int* wrow = wbase + kh * 48;
        #pragma unroll
        for (int jj = 0; jj < 12; jj++) {
            int4 w4 = *(const int4*)(wrow + jj * 4);
            #pragma unroll
            for (int i = 0; i < 7; i++) {
                int4 x4 = *(const int4*)(xrow + i * 16 + jj * 4);
                int a = acc[i];
                a = __dp4a(x4.x, w4.x, a);
                a = __dp4a(x4.y, w4.y, a);
                a = __dp4a(x4.z, w4.z, a);
                a = __dp4a(x4.w, w4.w, a);
                acc[i] = a;
            }
        }
    }

    #pragma unroll
    for (int i = 0; i < 7; i++) {
        int ow = owg * 7 + i;
        obase[ow] = __fadd_rn(__fmul_rn((float)acc[i], prod), bco);
    }
}

// ---------------------------------------------------------------------------
extern "C" void kernel_launch(void* const* d_in, const int* in_sizes, int n_in,
                              void* d_out, int out_size)
{
    const float* x    = (const float*)d_in[0];   // (8,64,28,28)
    const float* wgt  = (const float*)d_in[1];   // (64,64,3,3)
    const float* bias = (const float*)d_in[2];   // (64,)
    // d_in[3] = lut: lut[a+128,b+128] == a*b -> folded into integer MAC
    float* out = (float*)d_out;

    absmax_finalize_kernel<<<AB_GRID, 256>>>(x, wgt);
    quant_fused_kernel<<<(NX + NW + 255) / 256, 256>>>(x, wgt);
    conv_kernel<<<dim3(H_, B_), 256>>>(bias, out);
    (void)in_sizes; (void)n_in; (void)out_size;
}